// round 15
// baseline (speedup 1.0000x reference)
#include <cuda_runtime.h>
#include <cstdint>

typedef unsigned long long ull;

#define HD 128
#define DD 256

// ---------- packed f32x2 helpers (Blackwell sm_100+) ----------
__device__ __forceinline__ void fma2(ull &d, ull a, ull b) {
    asm("fma.rn.f32x2 %0, %1, %2, %0;" : "+l"(d) : "l"(a), "l"(b));
}
__device__ __forceinline__ ull add2(ull a, ull b) {
    ull d; asm("add.rn.f32x2 %0, %1, %2;" : "=l"(d) : "l"(a), "l"(b)); return d;
}
__device__ __forceinline__ float2 unpack2(ull u) {
    float2 r; asm("mov.b64 {%0, %1}, %2;" : "=f"(r.x), "=f"(r.y) : "l"(u)); return r;
}
__device__ __forceinline__ ull pack2(float lo, float hi) {
    ull d; asm("mov.b64 %0, {%1, %2};" : "=l"(d) : "f"(lo), "f"(hi)); return d;
}
__device__ __forceinline__ float tanh_approx(float x) {
    float r; asm("tanh.approx.f32 %0, %1;" : "=f"(r) : "f"(x)); return r;
}

// ---------- Kernel 1: xW = input @ Wi^T + bi, written into out[S,128] ----------
__global__ void __launch_bounds__(128) gemm_xw_kernel(
    const float* __restrict__ X,   // [S, 256]
    const float* __restrict__ Wi,  // [128, 256]
    const float* __restrict__ bi,  // [128]
    float* __restrict__ out, int S)
{
    __shared__ __align__(16) float xs[32][DD];
    const int h  = threadIdx.x;
    const int s0 = blockIdx.x * 32;

    const float4* Xg  = (const float4*)(X + (size_t)s0 * DD);
    float4*       xs4 = (float4*)&xs[0][0];
#pragma unroll
    for (int i = 0; i < 16; i++) xs4[h + 128 * i] = Xg[h + 128 * i];
    __syncthreads();

    float acc[32];
#pragma unroll
    for (int s = 0; s < 32; s++) acc[s] = 0.f;

    const float4* wr = (const float4*)(Wi + h * DD);
#pragma unroll 4
    for (int kk = 0; kk < DD / 4; kk++) {
        float4 wv = wr[kk];
#pragma unroll
        for (int s = 0; s < 32; s++) {
            float4 xv = *(const float4*)&xs[s][kk * 4];
            acc[s] = fmaf(wv.x, xv.x, acc[s]);
            acc[s] = fmaf(wv.y, xv.y, acc[s]);
            acc[s] = fmaf(wv.z, xv.z, acc[s]);
            acc[s] = fmaf(wv.w, xv.w, acc[s]);
        }
    }
    const float b = bi[h];
#pragma unroll
    for (int s = 0; s < 32; s++) out[(size_t)(s0 + s) * HD + h] = acc[s] + b;
}

// ---------- Kernel 2: sequential recurrence ----------
// R9 structure with one change (R15): only own GROUP 0 (16 floats, 4 LDS)
// is preloaded pre-barrier; own group 1 is loaded post-barrier in the
// FFMA2 issue gaps (rt-3 leaves 2 free slots per FMA) and its FMAs run at
// the END of the stream (data lands ~45 cyc, consumed at ~200 -- free).
// Pre-bar serial tail shrinks from ~40 to ~32 cyc/step.
// Everything else as R9/R14: weights pre-rotated (group g <-> K-group
// (2*wrp+g)&7), STS -> __syncwarp -> own-g0 LDS (syncwarp REQUIRED: no
// same-warp STS->LDS forwarding on sm_100a, proven R10), foreign groups
// depth-2 lookahead, 4-acc round-robin, MUFU tanh, batched STG.
__global__ void __launch_bounds__(128, 1) rnn_seq_kernel(
    const float* __restrict__ Wh,  // [128, 128]
    const float* __restrict__ bh,  // [128]
    const float* __restrict__ h0,  // [1, 128]
    float* out,                    // [S, 128]: xw in, h out
    float* hn, int S, int has_hn)
{
    __shared__ __align__(16) float sh[2][HD];
    const int j   = threadIdx.x;
    const int wrp = j >> 5;

    // pre-rotated weights: register group g <-> K-group (2*wrp+g)&7
    ull w[64];
#pragma unroll
    for (int g = 0; g < 8; g++) {
        const int kg = (2 * wrp + g) & 7;
        const ulonglong2* wp = (const ulonglong2*)(Wh + j * HD + kg * 16);
#pragma unroll
        for (int u = 0; u < 4; u++) {
            ulonglong2 v = wp[u];
            w[8 * g + 2 * u]     = v.x;
            w[8 * g + 2 * u + 1] = v.y;
        }
    }
    const float bj = bh[j];

    sh[0][j] = h0[j];

    float xwb[8], xwn[8], hv[8];
#pragma unroll
    for (int q = 0; q < 8; q++) xwb[q] = out[q * HD + j] + bj;

    __syncthreads();

    // preload own GROUP 0 only (16 floats) of buf 0
    ull own[8];
    {
        const ulonglong2* op = (const ulonglong2*)(&sh[0][wrp * 32]);
#pragma unroll
        for (int u = 0; u < 4; u++) { ulonglong2 v = op[u]; own[2*u] = v.x; own[2*u+1] = v.y; }
    }

    for (int t = 0; t < S; t += 8) {
        // prefetch the next 8 xw rows (consumed next outer iteration)
#pragma unroll
        for (int q = 0; q < 8; q++) {
            int tn = t + 8 + q;
            xwn[q] = (tn < S) ? out[(size_t)tn * HD + j] : 0.f;
        }
#pragma unroll
        for (int q = 0; q < 8; q++) {
            const int buf  = q & 1;        // t % 8 == 0, so step parity == q parity
            const int nbuf = buf ^ 1;
            const float* hb = &sh[buf][0];

            // a0 seeded with (xw + bias); 4-acc round-robin throughout
            ull a0 = pack2(xwb[q], 0.0f);
            ull a1 = 0, a2 = 0, a3 = 0;

            // own group 0 first: 8 FFMA2 straight from pre-bar registers
            fma2(a0, w[0], own[0]);  fma2(a1, w[1], own[1]);
            fma2(a2, w[2], own[2]);  fma2(a3, w[3], own[3]);
            fma2(a0, w[4], own[4]);  fma2(a1, w[5], own[5]);
            fma2(a2, w[6], own[6]);  fma2(a3, w[7], own[7]);

            // foreign g2/g3 loads + own g1 load (fit in FFMA2 issue gaps)
            const ulonglong2* g2p = (const ulonglong2*)(hb + (((2*wrp + 2) & 7) << 4));
            const ulonglong2* g3p = (const ulonglong2*)(hb + (((2*wrp + 3) & 7) << 4));
            ulonglong2 A0 = g2p[0], A1 = g2p[1], A2 = g2p[2], A3 = g2p[3];
            ulonglong2 B0 = g3p[0], B1 = g3p[1], B2 = g3p[2], B3 = g3p[3];
            const ulonglong2* o1p = (const ulonglong2*)(hb + wrp * 32 + 16);
            ulonglong2 P0 = o1p[0], P1 = o1p[1], P2 = o1p[2], P3 = o1p[3];

            // foreign groups 2..7, depth-2 lookahead
#pragma unroll
            for (int g = 2; g < 8; g++) {
                ulonglong2 N0, N1, N2, N3;
                if (g < 6) {
                    const ulonglong2* np = (const ulonglong2*)(hb + (((2*wrp + g + 2) & 7) << 4));
                    N0 = np[0]; N1 = np[1]; N2 = np[2]; N3 = np[3];
                }
                fma2(a0, w[8*g + 0], A0.x);
                fma2(a1, w[8*g + 1], A0.y);
                fma2(a2, w[8*g + 2], A1.x);
                fma2(a3, w[8*g + 3], A1.y);
                fma2(a0, w[8*g + 4], A2.x);
                fma2(a1, w[8*g + 5], A2.y);
                fma2(a2, w[8*g + 6], A3.x);
                fma2(a3, w[8*g + 7], A3.y);
                A0 = B0; A1 = B1; A2 = B2; A3 = B3;
                if (g < 6) { B0 = N0; B1 = N1; B2 = N2; B3 = N3; }
            }
            // own group 1 last (data landed long ago)
            fma2(a0, w[ 8], P0.x);  fma2(a1, w[ 9], P0.y);
            fma2(a2, w[10], P1.x);  fma2(a3, w[11], P1.y);
            fma2(a0, w[12], P2.x);  fma2(a1, w[13], P2.y);
            fma2(a2, w[14], P3.x);  fma2(a3, w[15], P3.y);

            // 2-level packed reduce, horizontal add, MUFU tanh
            float2 rr = unpack2(add2(add2(a0, a1), add2(a2, a3)));
            float hval = tanh_approx(rr.x + rr.y);
            hv[q] = hval;

            sh[nbuf][j] = hval;       // publish h_t
            __syncwarp();             // REQUIRED: no same-warp STS->LDS fwd (R10)
            // pre-bar preload of own GROUP 0 of the next buffer (4 LDS)
            {
                const ulonglong2* op = (const ulonglong2*)(&sh[nbuf][wrp * 32]);
#pragma unroll
                for (int u = 0; u < 4; u++) { ulonglong2 v = op[u]; own[2*u] = v.x; own[2*u+1] = v.y; }
            }
            __syncthreads();
        }
        // batched gmem stream of the 8 h rows (overlaps next prefetch)
#pragma unroll
        for (int q = 0; q < 8; q++) out[(size_t)(t + q) * HD + j] = hv[q];
#pragma unroll
        for (int q = 0; q < 8; q++) xwb[q] = xwn[q] + bj;
    }

    if (has_hn) hn[j] = hv[7];
}

// ---------- launcher ----------
extern "C" void kernel_launch(void* const* d_in, const int* in_sizes, int n_in,
                              void* d_out, int out_size)
{
    (void)n_in;
    const float* input = (const float*)d_in[0];  // [S, 256]
    const float* h0    = (const float*)d_in[1];  // [1, 128]
    const float* Wi    = (const float*)d_in[2];  // [128, 256]
    const float* bi    = (const float*)d_in[3];  // [128]
    const float* Wh    = (const float*)d_in[4];  // [128, 128]
    const float* bh    = (const float*)d_in[5];  // [128]
    float* out = (float*)d_out;

    const int S = in_sizes[0] / DD;
    const int has_hn = (out_size >= S * HD + HD) ? 1 : 0;
    float* hn = out + (size_t)S * HD;

    gemm_xw_kernel<<<(S + 31) / 32, 128>>>(input, Wi, bi, out, S);
    rnn_seq_kernel<<<1, 128>>>(Wh, bh, h0, out, hn, S, has_hn);
}

// round 16
// speedup vs baseline: 1.0185x; 1.0185x over previous
#include <cuda_runtime.h>
#include <cstdint>

typedef unsigned long long ull;

#define HD 128
#define DD 256

// ---------- packed f32x2 helpers (Blackwell sm_100+) ----------
__device__ __forceinline__ void fma2(ull &d, ull a, ull b) {
    asm("fma.rn.f32x2 %0, %1, %2, %0;" : "+l"(d) : "l"(a), "l"(b));
}
__device__ __forceinline__ ull add2(ull a, ull b) {
    ull d; asm("add.rn.f32x2 %0, %1, %2;" : "=l"(d) : "l"(a), "l"(b)); return d;
}
__device__ __forceinline__ float2 unpack2(ull u) {
    float2 r; asm("mov.b64 {%0, %1}, %2;" : "=f"(r.x), "=f"(r.y) : "l"(u)); return r;
}
__device__ __forceinline__ ull pack2(float lo, float hi) {
    ull d; asm("mov.b64 %0, {%1, %2};" : "=l"(d) : "f"(lo), "f"(hi)); return d;
}
__device__ __forceinline__ float tanh_approx(float x) {
    float r; asm("tanh.approx.f32 %0, %1;" : "=f"(r) : "f"(x)); return r;
}

// ---------- Kernel 1: xW = input @ Wi^T + bi, written into out[S,128] ----------
__global__ void __launch_bounds__(128) gemm_xw_kernel(
    const float* __restrict__ X,   // [S, 256]
    const float* __restrict__ Wi,  // [128, 256]
    const float* __restrict__ bi,  // [128]
    float* __restrict__ out, int S)
{
    __shared__ __align__(16) float xs[32][DD];
    const int h  = threadIdx.x;
    const int s0 = blockIdx.x * 32;

    const float4* Xg  = (const float4*)(X + (size_t)s0 * DD);
    float4*       xs4 = (float4*)&xs[0][0];
#pragma unroll
    for (int i = 0; i < 16; i++) xs4[h + 128 * i] = Xg[h + 128 * i];
    __syncthreads();

    float acc[32];
#pragma unroll
    for (int s = 0; s < 32; s++) acc[s] = 0.f;

    const float4* wr = (const float4*)(Wi + h * DD);
#pragma unroll 4
    for (int kk = 0; kk < DD / 4; kk++) {
        float4 wv = wr[kk];
#pragma unroll
        for (int s = 0; s < 32; s++) {
            float4 xv = *(const float4*)&xs[s][kk * 4];
            acc[s] = fmaf(wv.x, xv.x, acc[s]);
            acc[s] = fmaf(wv.y, xv.y, acc[s]);
            acc[s] = fmaf(wv.z, xv.z, acc[s]);
            acc[s] = fmaf(wv.w, xv.w, acc[s]);
        }
    }
    const float b = bi[h];
#pragma unroll
    for (int s = 0; s < 32; s++) out[(size_t)(s0 + s) * HD + h] = acc[s] + b;
}

// ---------- Kernel 2: sequential recurrence (FINAL — locked R9 design) ----------
// 128 threads = 4 warps (1/SMSP). Lane j owns output j; full Wh row j in
// registers, PRE-ROTATED so register group g <-> K-group (2*wrp+g)&7.
// Pre-barrier, each warp preloads its OWN 32 h-values (STS -> __syncwarp ->
// LDS; syncwarp REQUIRED: sm_100a has no same-warp STS->LDS forwarding,
// proven by R10's 0.19 rel_err) so post-barrier FMA starts from registers
// (48-cyc runway covering the foreign-LDS head; R15 proved halving it
// regresses); foreign groups stream with depth-2 lookahead. 4-accumulator
// round-robin (R11: fewer chains regress); xw+bias seeded into a0;
// single-MUFU tanh (rel_err ~4e-6, contractive recurrence); gmem h stores
// batched outside the inner loop; xw rows prefetched 8 steps ahead.
// Measured ~322 cyc/step: FFMA2 issue 192 (rt-3 RF-banking floor) +
// bar ~40 + serial tail ~90. Verified local optimum (R6/R11/R12/R13/R15
// all neutral-or-worse; R14 reproduced 12778 us to 0.01%).
__global__ void __launch_bounds__(128, 1) rnn_seq_kernel(
    const float* __restrict__ Wh,  // [128, 128]
    const float* __restrict__ bh,  // [128]
    const float* __restrict__ h0,  // [1, 128]
    float* out,                    // [S, 128]: xw in, h out
    float* hn, int S, int has_hn)
{
    __shared__ __align__(16) float sh[2][HD];
    const int j   = threadIdx.x;
    const int wrp = j >> 5;

    // pre-rotated weights: register group g <-> K-group (2*wrp+g)&7
    ull w[64];
#pragma unroll
    for (int g = 0; g < 8; g++) {
        const int kg = (2 * wrp + g) & 7;
        const ulonglong2* wp = (const ulonglong2*)(Wh + j * HD + kg * 16);
#pragma unroll
        for (int u = 0; u < 4; u++) {
            ulonglong2 v = wp[u];
            w[8 * g + 2 * u]     = v.x;
            w[8 * g + 2 * u + 1] = v.y;
        }
    }
    const float bj = bh[j];

    sh[0][j] = h0[j];

    float xwb[8], xwn[8], hv[8];
#pragma unroll
    for (int q = 0; q < 8; q++) xwb[q] = out[q * HD + j] + bj;

    __syncthreads();

    // preload own segment (rotated groups 0,1) of buf 0
    ull own[16];
    {
        const ulonglong2* op = (const ulonglong2*)(&sh[0][wrp * 32]);
#pragma unroll
        for (int u = 0; u < 8; u++) { ulonglong2 v = op[u]; own[2*u] = v.x; own[2*u+1] = v.y; }
    }

    for (int t = 0; t < S; t += 8) {
        // prefetch the next 8 xw rows (consumed next outer iteration)
#pragma unroll
        for (int q = 0; q < 8; q++) {
            int tn = t + 8 + q;
            xwn[q] = (tn < S) ? out[(size_t)tn * HD + j] : 0.f;
        }
#pragma unroll
        for (int q = 0; q < 8; q++) {
            const int buf  = q & 1;        // t % 8 == 0, so step parity == q parity
            const int nbuf = buf ^ 1;
            const float* hb = &sh[buf][0];

            // foreign groups, depth-2 lookahead (rotated groups 2..7)
            const ulonglong2* g2p = (const ulonglong2*)(hb + (((2*wrp + 2) & 7) << 4));
            const ulonglong2* g3p = (const ulonglong2*)(hb + (((2*wrp + 3) & 7) << 4));
            ulonglong2 A0 = g2p[0], A1 = g2p[1], A2 = g2p[2], A3 = g2p[3];
            ulonglong2 B0 = g3p[0], B1 = g3p[1], B2 = g3p[2], B3 = g3p[3];

            // a0 seeded with (xw + bias); 4-acc round-robin throughout
            ull a0 = pack2(xwb[q], 0.0f);
            ull a1 = 0, a2 = 0, a3 = 0;

            // own groups first: 16 FFMA2 straight from pre-bar registers
#pragma unroll
            for (int u = 0; u < 4; u++) {
                fma2(a0, w[4*u + 0], own[4*u + 0]);
                fma2(a1, w[4*u + 1], own[4*u + 1]);
                fma2(a2, w[4*u + 2], own[4*u + 2]);
                fma2(a3, w[4*u + 3], own[4*u + 3]);
            }
            // foreign groups 2..7
#pragma unroll
            for (int g = 2; g < 8; g++) {
                ulonglong2 N0, N1, N2, N3;
                if (g < 6) {
                    const ulonglong2* np = (const ulonglong2*)(hb + (((2*wrp + g + 2) & 7) << 4));
                    N0 = np[0]; N1 = np[1]; N2 = np[2]; N3 = np[3];
                }
                fma2(a0, w[8*g + 0], A0.x);
                fma2(a1, w[8*g + 1], A0.y);
                fma2(a2, w[8*g + 2], A1.x);
                fma2(a3, w[8*g + 3], A1.y);
                fma2(a0, w[8*g + 4], A2.x);
                fma2(a1, w[8*g + 5], A2.y);
                fma2(a2, w[8*g + 6], A3.x);
                fma2(a3, w[8*g + 7], A3.y);
                A0 = B0; A1 = B1; A2 = B2; A3 = B3;
                if (g < 6) { B0 = N0; B1 = N1; B2 = N2; B3 = N3; }
            }
            // 2-level packed reduce, horizontal add, MUFU tanh
            float2 rr = unpack2(add2(add2(a0, a1), add2(a2, a3)));
            float hval = tanh_approx(rr.x + rr.y);
            hv[q] = hval;

            sh[nbuf][j] = hval;       // publish h_t
            __syncwarp();             // REQUIRED: no same-warp STS->LDS fwd (R10)
            // pre-bar preload of OWN segment of the next buffer
            {
                const ulonglong2* op = (const ulonglong2*)(&sh[nbuf][wrp * 32]);
#pragma unroll
                for (int u = 0; u < 8; u++) { ulonglong2 v = op[u]; own[2*u] = v.x; own[2*u+1] = v.y; }
            }
            __syncthreads();
        }
        // batched gmem stream of the 8 h rows (overlaps next prefetch)
#pragma unroll
        for (int q = 0; q < 8; q++) out[(size_t)(t + q) * HD + j] = hv[q];
#pragma unroll
        for (int q = 0; q < 8; q++) xwb[q] = xwn[q] + bj;
    }

    if (has_hn) hn[j] = hv[7];
}

// ---------- launcher ----------
extern "C" void kernel_launch(void* const* d_in, const int* in_sizes, int n_in,
                              void* d_out, int out_size)
{
    (void)n_in;
    const float* input = (const float*)d_in[0];  // [S, 256]
    const float* h0    = (const float*)d_in[1];  // [1, 128]
    const float* Wi    = (const float*)d_in[2];  // [128, 256]
    const float* bi    = (const float*)d_in[3];  // [128]
    const float* Wh    = (const float*)d_in[4];  // [128, 128]
    const float* bh    = (const float*)d_in[5];  // [128]
    float* out = (float*)d_out;

    const int S = in_sizes[0] / DD;
    const int has_hn = (out_size >= S * HD + HD) ? 1 : 0;
    float* hn = out + (size_t)S * HD;

    gemm_xw_kernel<<<(S + 31) / 32, 128>>>(input, Wi, bi, out, S);
    rnn_seq_kernel<<<1, 128>>>(Wh, bh, h0, out, hn, S, has_hn);
}

// round 17
// speedup vs baseline: 1.0195x; 1.0010x over previous
#include <cuda_runtime.h>
#include <cstdint>

typedef unsigned long long ull;

#define HD 128
#define DD 256

// ---------- packed f32x2 helpers (Blackwell sm_100+) ----------
__device__ __forceinline__ void fma2(ull &d, ull a, ull b) {
    asm("fma.rn.f32x2 %0, %1, %2, %0;" : "+l"(d) : "l"(a), "l"(b));
}
__device__ __forceinline__ ull add2(ull a, ull b) {
    ull d; asm("add.rn.f32x2 %0, %1, %2;" : "=l"(d) : "l"(a), "l"(b)); return d;
}
__device__ __forceinline__ float2 unpack2(ull u) {
    float2 r; asm("mov.b64 {%0, %1}, %2;" : "=f"(r.x), "=f"(r.y) : "l"(u)); return r;
}
__device__ __forceinline__ ull pack2(float lo, float hi) {
    ull d; asm("mov.b64 %0, {%1, %2};" : "=l"(d) : "f"(lo), "f"(hi)); return d;
}
__device__ __forceinline__ float tanh_approx(float x) {
    float r; asm("tanh.approx.f32 %0, %1;" : "=f"(r) : "f"(x)); return r;
}

// ---------- Kernel 1: xW = input @ Wi^T + bi, written into out[S,128] ----------
__global__ void __launch_bounds__(128) gemm_xw_kernel(
    const float* __restrict__ X,   // [S, 256]
    const float* __restrict__ Wi,  // [128, 256]
    const float* __restrict__ bi,  // [128]
    float* __restrict__ out, int S)
{
    __shared__ __align__(16) float xs[32][DD];
    const int h  = threadIdx.x;
    const int s0 = blockIdx.x * 32;

    const float4* Xg  = (const float4*)(X + (size_t)s0 * DD);
    float4*       xs4 = (float4*)&xs[0][0];
#pragma unroll
    for (int i = 0; i < 16; i++) xs4[h + 128 * i] = Xg[h + 128 * i];
    __syncthreads();

    float acc[32];
#pragma unroll
    for (int s = 0; s < 32; s++) acc[s] = 0.f;

    const float4* wr = (const float4*)(Wi + h * DD);
#pragma unroll 4
    for (int kk = 0; kk < DD / 4; kk++) {
        float4 wv = wr[kk];
#pragma unroll
        for (int s = 0; s < 32; s++) {
            float4 xv = *(const float4*)&xs[s][kk * 4];
            acc[s] = fmaf(wv.x, xv.x, acc[s]);
            acc[s] = fmaf(wv.y, xv.y, acc[s]);
            acc[s] = fmaf(wv.z, xv.z, acc[s]);
            acc[s] = fmaf(wv.w, xv.w, acc[s]);
        }
    }
    const float b = bi[h];
#pragma unroll
    for (int s = 0; s < 32; s++) out[(size_t)(s0 + s) * HD + h] = acc[s] + b;
}

// ---------- Kernel 2: sequential recurrence (FINAL — locked R9 design) ----------
// 128 threads = 4 warps (1/SMSP). Lane j owns output j; full Wh row j in
// registers, PRE-ROTATED so register group g <-> K-group (2*wrp+g)&7.
// Pre-barrier, each warp preloads its OWN 32 h-values (STS -> __syncwarp ->
// LDS; syncwarp REQUIRED: sm_100a has no same-warp STS->LDS forwarding,
// proven by R10's 0.19 rel_err) so post-barrier FMA starts from registers
// (48-cyc runway covering the foreign-LDS head; R15 proved halving it
// regresses); foreign groups stream with depth-2 lookahead. 4-accumulator
// round-robin (R11: fewer chains regress); xw+bias seeded into a0;
// single-MUFU tanh (rel_err ~4e-6, contractive recurrence); gmem h stores
// batched outside the inner loop; xw rows prefetched 8 steps ahead.
// Measured ~322 cyc/step: FFMA2 issue 192 (rt-3 RF-banking floor) +
// bar ~40 + serial tail ~90. Verified local optimum: R6/R11/R12/R13/R15
// all neutral-or-worse; reproduced 12778/12779/12790 us across 3 runs.
__global__ void __launch_bounds__(128, 1) rnn_seq_kernel(
    const float* __restrict__ Wh,  // [128, 128]
    const float* __restrict__ bh,  // [128]
    const float* __restrict__ h0,  // [1, 128]
    float* out,                    // [S, 128]: xw in, h out
    float* hn, int S, int has_hn)
{
    __shared__ __align__(16) float sh[2][HD];
    const int j   = threadIdx.x;
    const int wrp = j >> 5;

    // pre-rotated weights: register group g <-> K-group (2*wrp+g)&7
    ull w[64];
#pragma unroll
    for (int g = 0; g < 8; g++) {
        const int kg = (2 * wrp + g) & 7;
        const ulonglong2* wp = (const ulonglong2*)(Wh + j * HD + kg * 16);
#pragma unroll
        for (int u = 0; u < 4; u++) {
            ulonglong2 v = wp[u];
            w[8 * g + 2 * u]     = v.x;
            w[8 * g + 2 * u + 1] = v.y;
        }
    }
    const float bj = bh[j];

    sh[0][j] = h0[j];

    float xwb[8], xwn[8], hv[8];
#pragma unroll
    for (int q = 0; q < 8; q++) xwb[q] = out[q * HD + j] + bj;

    __syncthreads();

    // preload own segment (rotated groups 0,1) of buf 0
    ull own[16];
    {
        const ulonglong2* op = (const ulonglong2*)(&sh[0][wrp * 32]);
#pragma unroll
        for (int u = 0; u < 8; u++) { ulonglong2 v = op[u]; own[2*u] = v.x; own[2*u+1] = v.y; }
    }

    for (int t = 0; t < S; t += 8) {
        // prefetch the next 8 xw rows (consumed next outer iteration)
#pragma unroll
        for (int q = 0; q < 8; q++) {
            int tn = t + 8 + q;
            xwn[q] = (tn < S) ? out[(size_t)tn * HD + j] : 0.f;
        }
#pragma unroll
        for (int q = 0; q < 8; q++) {
            const int buf  = q & 1;        // t % 8 == 0, so step parity == q parity
            const int nbuf = buf ^ 1;
            const float* hb = &sh[buf][0];

            // foreign groups, depth-2 lookahead (rotated groups 2..7)
            const ulonglong2* g2p = (const ulonglong2*)(hb + (((2*wrp + 2) & 7) << 4));
            const ulonglong2* g3p = (const ulonglong2*)(hb + (((2*wrp + 3) & 7) << 4));
            ulonglong2 A0 = g2p[0], A1 = g2p[1], A2 = g2p[2], A3 = g2p[3];
            ulonglong2 B0 = g3p[0], B1 = g3p[1], B2 = g3p[2], B3 = g3p[3];

            // a0 seeded with (xw + bias); 4-acc round-robin throughout
            ull a0 = pack2(xwb[q], 0.0f);
            ull a1 = 0, a2 = 0, a3 = 0;

            // own groups first: 16 FFMA2 straight from pre-bar registers
#pragma unroll
            for (int u = 0; u < 4; u++) {
                fma2(a0, w[4*u + 0], own[4*u + 0]);
                fma2(a1, w[4*u + 1], own[4*u + 1]);
                fma2(a2, w[4*u + 2], own[4*u + 2]);
                fma2(a3, w[4*u + 3], own[4*u + 3]);
            }
            // foreign groups 2..7
#pragma unroll
            for (int g = 2; g < 8; g++) {
                ulonglong2 N0, N1, N2, N3;
                if (g < 6) {
                    const ulonglong2* np = (const ulonglong2*)(hb + (((2*wrp + g + 2) & 7) << 4));
                    N0 = np[0]; N1 = np[1]; N2 = np[2]; N3 = np[3];
                }
                fma2(a0, w[8*g + 0], A0.x);
                fma2(a1, w[8*g + 1], A0.y);
                fma2(a2, w[8*g + 2], A1.x);
                fma2(a3, w[8*g + 3], A1.y);
                fma2(a0, w[8*g + 4], A2.x);
                fma2(a1, w[8*g + 5], A2.y);
                fma2(a2, w[8*g + 6], A3.x);
                fma2(a3, w[8*g + 7], A3.y);
                A0 = B0; A1 = B1; A2 = B2; A3 = B3;
                if (g < 6) { B0 = N0; B1 = N1; B2 = N2; B3 = N3; }
            }
            // 2-level packed reduce, horizontal add, MUFU tanh
            float2 rr = unpack2(add2(add2(a0, a1), add2(a2, a3)));
            float hval = tanh_approx(rr.x + rr.y);
            hv[q] = hval;

            sh[nbuf][j] = hval;       // publish h_t
            __syncwarp();             // REQUIRED: no same-warp STS->LDS fwd (R10)
            // pre-bar preload of OWN segment of the next buffer
            {
                const ulonglong2* op = (const ulonglong2*)(&sh[nbuf][wrp * 32]);
#pragma unroll
                for (int u = 0; u < 8; u++) { ulonglong2 v = op[u]; own[2*u] = v.x; own[2*u+1] = v.y; }
            }
            __syncthreads();
        }
        // batched gmem stream of the 8 h rows (overlaps next prefetch)
#pragma unroll
        for (int q = 0; q < 8; q++) out[(size_t)(t + q) * HD + j] = hv[q];
#pragma unroll
        for (int q = 0; q < 8; q++) xwb[q] = xwn[q] + bj;
    }

    if (has_hn) hn[j] = hv[7];
}

// ---------- launcher ----------
extern "C" void kernel_launch(void* const* d_in, const int* in_sizes, int n_in,
                              void* d_out, int out_size)
{
    (void)n_in;
    const float* input = (const float*)d_in[0];  // [S, 256]
    const float* h0    = (const float*)d_in[1];  // [1, 128]
    const float* Wi    = (const float*)d_in[2];  // [128, 256]
    const float* bi    = (const float*)d_in[3];  // [128]
    const float* Wh    = (const float*)d_in[4];  // [128, 128]
    const float* bh    = (const float*)d_in[5];  // [128]
    float* out = (float*)d_out;

    const int S = in_sizes[0] / DD;
    const int has_hn = (out_size >= S * HD + HD) ? 1 : 0;
    float* hn = out + (size_t)S * HD;

    gemm_xw_kernel<<<(S + 31) / 32, 128>>>(input, Wi, bi, out, S);
    rnn_seq_kernel<<<1, 128>>>(Wh, bh, h0, out, hn, S, has_hn);
}